// round 13
// baseline (speedup 1.0000x reference)
#include <cuda_runtime.h>
#include <cstdint>

#define NFEAT 784
#define NCLS  10
#define KC    16
#define NT    49                     // 784 / 16
#define TPB   224                    // 7 warps
#define NWARP 7
#define RPT   2
#define ROWSPW 64                    // rows per warp
#define ROWSPC (NWARP * ROWSPW)      // 448 rows per CTA -> grid 147
#define XSTR  20                     // 16 + 4 pad: conflict-free LDS.128
#define NBUF  4                      // warp-private ring depth
#define RINGF (NBUF * ROWSPW * XSTR)               // 5120 floats per warp
#define XS_FLOATS (NWARP * RINGF)                  // 35840
#define RED_FLOATS (NWARP * NCLS)                  // 70
#define SMEM_FLOATS (XS_FLOATS + RED_FLOATS + 2)
#define SMEM_BYTES  (SMEM_FLOATS * 4)              // ~140.3 KB -> L1D ~87KB

// Folded matrix in GMEM; L1-resident after first sweep. Every CTA writes
// bitwise-identical values (benign race); reads only after own-CTA barrier.
__device__ float g_A[NCLS * NFEAT];

// ---------------------------------------------------------------------------
__device__ __forceinline__ void cp_async16(uint32_t saddr, const void* gptr) {
    asm volatile("cp.async.cg.shared.global [%0], [%1], 16;\n"
                 :: "r"(saddr), "l"(gptr));
}
#define CP_COMMIT() asm volatile("cp.async.commit_group;\n" ::: "memory")
#define CP_WAIT(n)  asm volatile("cp.async.wait_group %0;\n" :: "n"(n) : "memory")
#define FMA_F32X2(d, a, b) \
    asm volatile("fma.rn.f32x2 %0, %1, %2, %0;" : "+l"(d) : "l"(a), "l"(b))

extern __shared__ float smem[];

// Warp-private stage of tile t: 64 rows x 16 k, 8 chunks/lane, one group.
__device__ __forceinline__ void issue_tile(const float* __restrict__ x,
                                           float* xw, int wrow0, int Brows,
                                           int lane, int t) {
    const int k0 = t * KC;
    float* xb = xw + (t & (NBUF - 1)) * (ROWSPW * XSTR);
#pragma unroll
    for (int i = 0; i < 8; ++i) {
        int g  = lane + i * 32;        // 0..255: (row, 16B-chunk)
        int r  = g >> 2;
        int ch = g & 3;
        int row = wrow0 + r;
        if (row >= Brows) row = Brows - 1;   // clamp (reads discarded)
        const float* gp = x + (size_t)row * NFEAT + k0 + ch * 4;
        uint32_t sa = (uint32_t)__cvta_generic_to_shared(xb + r * XSTR + ch * 4);
        cp_async16(sa, gp);
    }
    CP_COMMIT();
}

// ---------------------------------------------------------------------------
// R5 structure, A moved off the smem crossbar onto the L1 broadcast path:
// barrier-free warp-private cp.async rings for x; A read via uniform
// LDG.E.CONSTANT.128 (__ldg). No fences, no L1 flush, no aliasing.
// ---------------------------------------------------------------------------
__global__ void __launch_bounds__(TPB, 1)
fused_kernel(const float* __restrict__ x,
             const float* __restrict__ W,
             const float* __restrict__ Bsp,
             const float* __restrict__ fcw,
             const float* __restrict__ fcb,
             float* __restrict__ out, int Brows)
{
    float* red = smem + XS_FLOATS;            // [7][10]

    const int tid  = threadIdx.x;
    const int wid  = tid >> 5;
    const int lane = tid & 31;
    const int wrow0 = blockIdx.x * ROWSPC + wid * ROWSPW;
    float* xw = smem + wid * RINGF;

    // Kick DRAM immediately: 3 tiles in flight per warp while A is built.
    issue_tile(x, xw, wrow0, Brows, lane, 0);
    issue_tile(x, xw, wrow0, Brows, lane, 1);
    issue_tile(x, xw, wrow0, Brows, lane, 2);

    // ---- build A (redundant per CTA, coalesced STG) + bias partials ----
    float part[NCLS];
#pragma unroll
    for (int c = 0; c < NCLS; ++c) part[c] = 0.f;

    for (int k = tid; k < NFEAT; k += TPB) {
        // scatter column map (faithful to the reference's i=782 wraparound bug)
        int c0i = (k == NFEAT - 2) ? 0 : k;
        int c1i = (k == NFEAT - 2) ? 1 : ((k + 1 == NFEAT) ? 0 : k + 1);
        float w0 = W[2*k],   w1 = W[2*k+1];
        float b0 = Bsp[2*k], b1 = Bsp[2*k+1];
#pragma unroll
        for (int c = 0; c < NCLS; ++c) {
            float f0 = __ldg(fcw + c * NFEAT + c0i);
            float f1 = __ldg(fcw + c * NFEAT + c1i);
            g_A[c * NFEAT + k] = f0 * w0 + f1 * w1;   // lanes k-contiguous
            part[c] += f0 * b0 + f1 * b1;
        }
    }
#pragma unroll
    for (int off = 16; off; off >>= 1)
#pragma unroll
        for (int c = 0; c < NCLS; ++c)
            part[c] += __shfl_down_sync(0xffffffffu, part[c], off);
    if (lane == 0)
#pragma unroll
        for (int c = 0; c < NCLS; ++c) red[wid * NCLS + c] = part[c];
    __syncthreads();     // block-scope fence: own-CTA g_A stores + red visible

    // ---- barrier-free main GEMV loop: 2 rows/thread, A via __ldg ----
    unsigned long long acc0[NCLS], acc1[NCLS];
#pragma unroll
    for (int c = 0; c < NCLS; ++c) { acc0[c] = 0ULL; acc1[c] = 0ULL; }

    for (int t = 0; t < NT; ++t) {
        if (t < NT - 2)       { CP_WAIT(2); }
        else if (t == NT - 2) { CP_WAIT(1); }
        else                  { CP_WAIT(0); }

        const float* xb  = xw + (t & (NBUF - 1)) * (ROWSPW * XSTR);
        const float* xr0 = xb + lane * XSTR;
        const float* xr1 = xb + (32 + lane) * XSTR;
        const int k0 = t * KC;
#pragma unroll
        for (int kc = 0; kc < 4; ++kc) {
            ulonglong2 v0 = *(const ulonglong2*)(xr0 + kc * 4);
            ulonglong2 v1 = *(const ulonglong2*)(xr1 + kc * 4);
#pragma unroll
            for (int c = 0; c < NCLS; ++c) {
                ulonglong2 av = __ldg((const ulonglong2*)
                                      (g_A + c * NFEAT + k0 + kc * 4));
                FMA_F32X2(acc0[c], v0.x, av.x);
                FMA_F32X2(acc0[c], v0.y, av.y);
                FMA_F32X2(acc1[c], v1.x, av.x);
                FMA_F32X2(acc1[c], v1.y, av.y);
            }
        }
        if (t + 3 < NT) issue_tile(x, xw, wrow0, Brows, lane, t + 3);
    }

    // ---- epilogue: bias from red (broadcast reads), softmax, store ----
    float c0v[NCLS];
#pragma unroll
    for (int c = 0; c < NCLS; ++c) {
        float s = __ldg(fcb + c);
#pragma unroll
        for (int w = 0; w < NWARP; ++w) s += red[w * NCLS + c];
        c0v[c] = s;
    }

#pragma unroll
    for (int rsel = 0; rsel < RPT; ++rsel) {
        const unsigned long long* acc = rsel ? acc1 : acc0;
        float logit[NCLS];
#pragma unroll
        for (int c = 0; c < NCLS; ++c) {
            float lo = __uint_as_float((unsigned)(acc[c] & 0xffffffffu));
            float hi = __uint_as_float((unsigned)(acc[c] >> 32));
            logit[c] = lo + hi + c0v[c];
        }
        float m = logit[0];
#pragma unroll
        for (int c = 1; c < NCLS; ++c) m = fmaxf(m, logit[c]);
        float ssum = 0.f;
#pragma unroll
        for (int c = 0; c < NCLS; ++c) { logit[c] = __expf(logit[c] - m); ssum += logit[c]; }
        float inv = 1.0f / ssum;

        const int row = wrow0 + lane + rsel * 32;
        if (row < Brows) {
            float2* po = (float2*)(out + (size_t)row * NCLS);
#pragma unroll
            for (int c = 0; c < NCLS; c += 2)
                po[c >> 1] = make_float2(logit[c] * inv, logit[c + 1] * inv);
        }
    }
}

// ---------------------------------------------------------------------------
extern "C" void kernel_launch(void* const* d_in, const int* in_sizes, int n_in,
                              void* d_out, int out_size) {
    const float* x   = (const float*)d_in[0];
    const float* W   = (const float*)d_in[1];
    const float* bsp = (const float*)d_in[2];
    const float* fcw = (const float*)d_in[3];
    const float* fcb = (const float*)d_in[4];
    float* out = (float*)d_out;
    const int Brows = in_sizes[0] / NFEAT;

    cudaFuncSetAttribute(fused_kernel,
                         cudaFuncAttributeMaxDynamicSharedMemorySize, SMEM_BYTES);

    const int grid = (Brows + ROWSPC - 1) / ROWSPC;   // 147 for B=65536
    fused_kernel<<<grid, TPB, SMEM_BYTES>>>(x, W, bsp, fcw, fcb, out, Brows);
}

// round 15
// speedup vs baseline: 1.9183x; 1.9183x over previous
#include <cuda_runtime.h>
#include <cstdint>

#define NFEAT 784
#define NCLS  10
#define KC    16
#define NT    49                     // 784 / 16
#define TPB   448                    // 14 warps
#define NWARP 14
#define ROWSPW 32                    // rows per warp
#define ROWSPC (NWARP * ROWSPW)      // 448 rows per CTA -> grid 147
#define XSTR  16                     // floats per row slot (no pad needed)
#define SLOTF (ROWSPW * XSTR)        // 512 floats = 2KB per tile slot
#define NBUF  4                      // warp-private ring depth
#define RINGF (NBUF * SLOTF)         // 2048 floats per warp
#define XS_FLOATS (NWARP * RINGF)    // 28672
#define AS_FLOATS (NCLS * NFEAT)     // 7840
#define RED_FLOATS (NWARP * NCLS)    // 140
#define SMEM_FLOATS (XS_FLOATS + AS_FLOATS + RED_FLOATS + 2)
#define SMEM_BYTES  (SMEM_FLOATS * 4)    // ~146.6 KB -> 1 CTA/SM

// ---------------------------------------------------------------------------
__device__ __forceinline__ void cp_async16(uint32_t saddr, const void* gptr) {
    asm volatile("cp.async.cg.shared.global [%0], [%1], 16;\n"
                 :: "r"(saddr), "l"(gptr));
}
#define CP_COMMIT() asm volatile("cp.async.commit_group;\n" ::: "memory")
#define CP_WAIT(n)  asm volatile("cp.async.wait_group %0;\n" :: "n"(n) : "memory")
#define FMA_F32X2(d, a, b) \
    asm volatile("fma.rn.f32x2 %0, %1, %2, %0;" : "+l"(d) : "l"(a), "l"(b))

extern __shared__ float smem[];

// Warp-private stage of tile t: 32 rows x 16 k, 4 chunks/lane, one group.
__device__ __forceinline__ void issue_tile(const float* __restrict__ x,
                                           float* xw, int wrow0, int Brows,
                                           int lane, int t) {
    const int k0 = t * KC;
    float* xb = xw + (t & (NBUF - 1)) * SLOTF;
#pragma unroll
    for (int i = 0; i < 4; ++i) {
        int g  = lane + i * 32;        // 0..127: (row, 16B-chunk)
        int r  = g >> 2;
        int ch = g & 3;
        int row = wrow0 + r;
        if (row >= Brows) row = Brows - 1;   // clamp (reads discarded)
        const float* gp = x + (size_t)row * NFEAT + k0 + ch * 4;
        uint32_t sa = (uint32_t)__cvta_generic_to_shared(xb + r * XSTR + ch * 4);
        cp_async16(sa, gp);
    }
    CP_COMMIT();
}

// ---------------------------------------------------------------------------
// (row,k)-tiled lane layout: lane = sr*4+kg owns rows {sr+8*ri} and k-slice
// kg*4..kg*4+3 of each tile. One LDS.128 of A per class serves the whole
// warp (4 distinct 16B slices, bank-disjoint -> ~1 wavefront vs 40 pure
// broadcasts). 14 warps, barrier-free warp-private cp.async rings, partial
// k-sums folded with 2 shfl.xor per (class,row) in the epilogue.
// ---------------------------------------------------------------------------
__global__ void __launch_bounds__(TPB, 1)
fused_kernel(const float* __restrict__ x,
             const float* __restrict__ W,
             const float* __restrict__ Bsp,
             const float* __restrict__ fcw,
             const float* __restrict__ fcb,
             float* __restrict__ out, int Brows)
{
    float* As  = smem + XS_FLOATS;            // [10][784] class-contiguous
    float* red = As + AS_FLOATS;              // [14][10]

    const int tid  = threadIdx.x;
    const int wid  = tid >> 5;
    const int lane = tid & 31;
    const int sr   = lane >> 2;               // sub-row 0..7
    const int kg   = lane & 3;                // k-group 0..3 (4 floats)
    const int wrow0 = blockIdx.x * ROWSPC + wid * ROWSPW;
    float* xw = smem + wid * RINGF;

    // Kick DRAM immediately: 3 tiles in flight per warp while A is built.
    issue_tile(x, xw, wrow0, Brows, lane, 0);
    issue_tile(x, xw, wrow0, Brows, lane, 1);
    issue_tile(x, xw, wrow0, Brows, lane, 2);

    // ---- build A[c][k] and per-warp bias partials in shared ----
    float part[NCLS];
#pragma unroll
    for (int c = 0; c < NCLS; ++c) part[c] = 0.f;

    for (int k = tid; k < NFEAT; k += TPB) {
        // scatter column map (faithful to the reference's i=782 wraparound bug)
        int c0i = (k == NFEAT - 2) ? 0 : k;
        int c1i = (k == NFEAT - 2) ? 1 : ((k + 1 == NFEAT) ? 0 : k + 1);
        float w0 = W[2*k],   w1 = W[2*k+1];
        float b0 = Bsp[2*k], b1 = Bsp[2*k+1];
#pragma unroll
        for (int c = 0; c < NCLS; ++c) {
            float f0 = __ldg(fcw + c * NFEAT + c0i);
            float f1 = __ldg(fcw + c * NFEAT + c1i);
            As[c * NFEAT + k] = f0 * w0 + f1 * w1;
            part[c] += f0 * b0 + f1 * b1;
        }
    }
#pragma unroll
    for (int off = 16; off; off >>= 1)
#pragma unroll
        for (int c = 0; c < NCLS; ++c)
            part[c] += __shfl_down_sync(0xffffffffu, part[c], off);
    if (lane == 0)
#pragma unroll
        for (int c = 0; c < NCLS; ++c) red[wid * NCLS + c] = part[c];
    __syncthreads();     // the ONLY barrier: A + red visible to all warps

    // ---- barrier-free main loop: 4 row-slots/lane, k-slice per lane ----
    unsigned long long acc[NCLS * 4];         // [c][ri] packed f32x2 over k-pair
#pragma unroll
    for (int i = 0; i < NCLS * 4; ++i) acc[i] = 0ULL;

    for (int t = 0; t < NT; ++t) {
        if (t < NT - 2)       { CP_WAIT(2); }
        else if (t == NT - 2) { CP_WAIT(1); }
        else                  { CP_WAIT(0); }

        const float* xb = xw + (t & (NBUF - 1)) * SLOTF;
        // x: lane reads its 16B k-slice of rows sr, sr+8, sr+16, sr+24
        ulonglong2 xv[4];
#pragma unroll
        for (int ri = 0; ri < 4; ++ri)
            xv[ri] = *(const ulonglong2*)(xb + (sr + 8 * ri) * XSTR + kg * 4);

        const float* Ab = As + t * KC + kg * 4;
#pragma unroll
        for (int c = 0; c < NCLS; ++c) {
            // ONE warp-wide LDS.128 per class: 4 distinct 16B slices (64B total)
            ulonglong2 av = *(const ulonglong2*)(Ab + c * NFEAT);
#pragma unroll
            for (int ri = 0; ri < 4; ++ri) {
                FMA_F32X2(acc[c * 4 + ri], xv[ri].x, av.x);
                FMA_F32X2(acc[c * 4 + ri], xv[ri].y, av.y);
            }
        }
        if (t + 3 < NT) issue_tile(x, xw, wrow0, Brows, lane, t + 3);
    }

    // ---- epilogue: fold k-pairs + kg lanes, bias, softmax, store ----
    float c0v[NCLS];
#pragma unroll
    for (int c = 0; c < NCLS; ++c) {
        float s = __ldg(fcb + c);
#pragma unroll
        for (int w = 0; w < NWARP; ++w) s += red[w * NCLS + c];
        c0v[c] = s;
    }

    // lane (sr,kg) ends up owning row sr + 8*kg  (takes ri == kg)
    float logit[NCLS];
#pragma unroll
    for (int c = 0; c < NCLS; ++c) {
#pragma unroll
        for (int ri = 0; ri < 4; ++ri) {
            unsigned long long a = acc[c * 4 + ri];
            float v = __uint_as_float((unsigned)(a & 0xffffffffu))
                    + __uint_as_float((unsigned)(a >> 32));
            v += __shfl_xor_sync(0xffffffffu, v, 1);
            v += __shfl_xor_sync(0xffffffffu, v, 2);
            if (ri == kg) logit[c] = v + c0v[c];
        }
    }

    float m = logit[0];
#pragma unroll
    for (int c = 1; c < NCLS; ++c) m = fmaxf(m, logit[c]);
    float ssum = 0.f;
#pragma unroll
    for (int c = 0; c < NCLS; ++c) { logit[c] = __expf(logit[c] - m); ssum += logit[c]; }
    float inv = 1.0f / ssum;

    const int row = wrow0 + sr + 8 * kg;
    if (row < Brows) {
        float2* po = (float2*)(out + (size_t)row * NCLS);
#pragma unroll
        for (int c = 0; c < NCLS; c += 2)
            po[c >> 1] = make_float2(logit[c] * inv, logit[c + 1] * inv);
    }
}

// ---------------------------------------------------------------------------
extern "C" void kernel_launch(void* const* d_in, const int* in_sizes, int n_in,
                              void* d_out, int out_size) {
    const float* x   = (const float*)d_in[0];
    const float* W   = (const float*)d_in[1];
    const float* bsp = (const float*)d_in[2];
    const float* fcw = (const float*)d_in[3];
    const float* fcb = (const float*)d_in[4];
    float* out = (float*)d_out;
    const int Brows = in_sizes[0] / NFEAT;

    cudaFuncSetAttribute(fused_kernel,
                         cudaFuncAttributeMaxDynamicSharedMemorySize, SMEM_BYTES);

    const int grid = (Brows + ROWSPC - 1) / ROWSPC;   // 147 for B=65536
    fused_kernel<<<grid, TPB, SMEM_BYTES>>>(x, W, bsp, fcw, fcb, out, Brows);
}